// round 15
// baseline (speedup 1.0000x reference)
#include <cuda_runtime.h>
#include <cuda_fp16.h>
#include <math.h>
#include <stdint.h>

// ---------------- problem constants ----------------
#define NB      2
#define CIN     256
#define KTOT    2304
#define TOTCELL 20460
#define NANCH   (TOTCELL*3)
#define TRUNK_SZ 589824
#define KT_N     36
#define WA_BLOB  8192                      // halves per (128-blk, ktile)
#define WA_BLK   (KT_N*WA_BLOB)
#define WA_TOT   (18*WA_BLK)
#define NSTAGE   3
#define A_STG_B  8192                      // bytes per A stage (64 rows x 64 k fp16)
#define HALO_B   27200                     // bytes per halo buffer (340 rows * 80B)
#define HALO_OFF (NSTAGE*A_STG_B)          // 24576
#define DSM_B    (HALO_OFF + 2*HALO_B)     // 78976
#define MP2      72                        // epilogue staging stride (halves)
#define NPATCH   87

__constant__ int   c_H[5]    = {6,12,24,48,96};
__constant__ int   c_W[5]    = {10,20,40,80,160};
__constant__ int   c_HW[5]   = {60,240,960,3840,15360};
__constant__ int   c_CO[5]   = {0,60,300,1260,5100};
__constant__ int   c_PTC[5]  = {0,1,3,9,27};     // 8x32 patch offsets (87 total)
__constant__ int   c_PCOL[5] = {1,1,2,3,5};
__constant__ int   c_PT[5]   = {0,2,10,40,160};  // input-transpose tiles
__constant__ float c_S[5]    = {128.f,64.f,32.f,16.f,8.f};
__constant__ int   c_CHF[36] = {0,-1,1,-1,-1,-1,-1,2,-1,-1,-1,3,-1,-1,-1,-1,4,-1,-1,-1,
                                5,-1,-1,-1,-1,6,-1,-1,-1,7,-1,-1,-1,-1,-1,-1};

// ---------------- device scratch ----------------
__device__ __align__(16) __half g_wA[WA_TOT];
__device__ __align__(16) __half g_actI[NB*TOTCELL*CIN];
__device__ __align__(16) __half g_c0[NB*TOTCELL*CIN];
__device__ __align__(16) __half g_c1[NB*TOTCELL*CIN];
__device__ __align__(16) __half g_b0[NB*TOTCELL*CIN];
__device__ __align__(16) __half g_b1[NB*TOTCELL*CIN];
__device__ float  g_cls [NB*NANCH*2];
__device__ float  g_num [NB*NANCH*2];
__device__ float  g_iouP[NB*NANCH*2];
__device__ float  g_off [NB*NANCH*8];
__device__ float  g_lab [NB*NANCH*2];
__device__ float  g_tgt [NB*NANCH*8];
__device__ double g_acc[6];

// ---------------- helpers ----------------
__device__ __forceinline__ uint32_t smem_u32(const void* p) {
    uint32_t a;
    asm("{ .reg .u64 t; cvta.to.shared.u64 t, %1; cvt.u32.u64 %0, t; }" : "=r"(a) : "l"(p));
    return a;
}
__device__ __forceinline__ void cpa16(uint32_t dst, const void* src, int sz) {
    asm volatile("cp.async.cg.shared.global [%0], [%1], 16, %2;"
                 :: "r"(dst), "l"(src), "r"(sz) : "memory");
}
__device__ __forceinline__ void cpa16_ca(uint32_t dst, const void* src, int sz) {
    asm volatile("cp.async.ca.shared.global [%0], [%1], 16, %2;"
                 :: "r"(dst), "l"(src), "r"(sz) : "memory");
}
#define CP_COMMIT() asm volatile("cp.async.commit_group;" ::: "memory")
#define CP_WAIT1()  asm volatile("cp.async.wait_group 1;"  ::: "memory")
#define CP_WAIT0()  asm volatile("cp.async.wait_group 0;"  ::: "memory")

// ---------- weight transpose into m16n8k16 A-fragment order (fp16) --------
__global__ void transpose_w_k(const float* __restrict__ cls_w, const float* __restrict__ box_w,
                              const float* __restrict__ score_w, const float* __restrict__ num_w,
                              const float* __restrict__ bpred_w, const float* __restrict__ iou_w)
{
    if (blockIdx.x == 0 && threadIdx.x < 6) g_acc[threadIdx.x] = 0.0;
    int i = blockIdx.x * 256 + threadIdx.x;
    if (i >= WA_TOT) return;
    int blk = i / WA_BLK;
    int rem = i - blk * WA_BLK;
    int kt  = rem / WA_BLOB;
    int r2  = rem - kt * WA_BLOB;
    int ks   = r2 >> 11;
    int mf8  = (r2 >> 8) & 7;
    int lane = (r2 >> 3) & 31;
    int h    = r2 & 7;
    int m  = mf8 * 16 + (lane >> 2) + ((h >> 1) & 1) * 8;
    int kl = ks * 16 + (lane & 3) * 2 + (h & 1) + ((h >> 2) & 1) * 8;
    int kp = kt * 64 + kl;
    int kb = kp >> 5, ci = kp & 31;
    int chunk = kb / 9, tap = kb - chunk * 9;
    int korig = (chunk * 32 + ci) * 9 + tap;

    float v = 0.f;
    if (blk < 16) {
        int L = blk >> 1; int mrow = (blk & 1) * 128 + m;
        const float* base = (L < 4) ? cls_w + (long long)L * TRUNK_SZ
                                    : box_w + (long long)(L - 4) * TRUNK_SZ;
        v = base[(long long)mrow * KTOT + korig];
    } else if (blk == 16) {
        if (m < 6)       v = score_w[(long long)m * KTOT + korig];
        else if (m < 12) v = num_w[(long long)(m - 6) * KTOT + korig];
    } else {
        if (m < 24)      v = bpred_w[(long long)m * KTOT + korig];
        else if (m < 30) v = iou_w[(long long)(m - 24) * KTOT + korig];
    }
    g_wA[i] = __float2half_rn(v);
}

// ---------- input transpose ----------
__global__ void transpose_in_k(const float* __restrict__ f0, const float* __restrict__ f1,
                               const float* __restrict__ f2, const float* __restrict__ f3,
                               const float* __restrict__ f4)
{
    __shared__ float tile[32][33];
    int bx = blockIdx.x, lvl = 0;
    #pragma unroll
    for (int l = 1; l < 5; l++) if (bx >= c_PT[l]) lvl = l;
    const int HW = c_HW[lvl];
    const int p0 = (bx - c_PT[lvl]) * 32;
    const int c0 = blockIdx.y * 32;
    const int z  = blockIdx.z;
    const float* src = (lvl==0?f0:lvl==1?f1:lvl==2?f2:lvl==3?f3:f4) + (long long)z*256*HW;
    int tx = threadIdx.x, ty = threadIdx.y;
    for (int r = ty; r < 32; r += 8) {
        int p = p0 + tx;
        tile[r][tx] = (p < HW) ? src[(long long)(c0 + r) * HW + p] : 0.f;
    }
    __syncthreads();
    __half* dst = g_actI + ((long long)z * TOTCELL + c_CO[lvl]) * 256;
    for (int j = ty; j < 32; j += 8) {
        int p = p0 + j;
        if (p < HW) dst[(long long)p * 256 + c0 + tx] = __float2half_rn(tile[tx][j]);
    }
}

// ---------- per-branch config ----------
struct BCfg {
    const __half* in;
    int wblk;
    const float* ba; const float* bb;
    int msplit;
    void* oa; void* ob;
    int sa, sb, aa, ab, Mtot, outHalf, mlim;
};

// ---------- fp16 mma.sync conv: CTA 64(M) x 8x32 patch, warp tile 32x64 ---
__global__ void __launch_bounds__(256, 2) conv_mma(BCfg c0, BCfg c1, int mblocks)
{
    extern __shared__ __align__(16) __half dsm[];
    const uint32_t sm0   = smem_u32(dsm);
    const uint32_t haloB = sm0 + HALO_OFF;
    const int tid  = threadIdx.x;
    const int lane = tid & 31;
    const int wid  = tid >> 5;
    const int warpM = wid & 1;          // 0..1 (32 M each)
    const int warpN = wid >> 1;         // 0..3 (64 N each)

    const int yb = blockIdx.y;
    const int mb = (mblocks == 4) ? (yb & 3) : 0;
    const BCfg& C = ((mblocks == 4 ? (yb >> 2) : yb) ? c1 : c0);
    const int mhalf = mb & 1;
    const int m0 = mb * 64;

    int bx = blockIdx.x, lvl = 0;
    #pragma unroll
    for (int l = 1; l < 5; l++) if (bx >= c_PTC[l]) lvl = l;
    const int H = c_H[lvl], W = c_W[lvl];
    const int pidx = bx - c_PTC[lvl];
    const int pcw  = c_PCOL[lvl];
    const int prow = pidx / pcw;
    const int py0  = prow * 8;
    const int px0  = (pidx - prow * pcw) * 32;
    const int z  = blockIdx.z;
    const long long zco = (long long)z * TOTCELL + c_CO[lvl];
    const __half* actL = C.in + zco * 256;
    const __half* wA = g_wA + (size_t)(C.wblk + (mb >> 1)) * WA_BLK;
    const bool wact = (warpM * 32) < C.mlim;

    // ldmatrix row bases (bytes into a halo buffer; tap-independent)
    const int gq = lane >> 3, rr = lane & 7;
    int hbase[4];
    #pragma unroll
    for (int np = 0; np < 4; np++) {
        int nn = warpN * 64 + (np * 2 + (gq >> 1)) * 8 + rr;
        hbase[np] = (((nn >> 5) + 1) * 34 + ((nn & 31) + 1)) * 80 + (gq & 1) * 16;
    }

    auto fill = [&](int kt) {
        const uint32_t As = sm0 + (kt % NSTAGE) * A_STG_B;
        const __half* wsrc = wA + (size_t)kt * WA_BLOB;
        #pragma unroll
        for (int i = 0; i < 2; i++) {
            int idx = i * 256 + tid;           // 0..511
            int ks = idx >> 7, mf8loc = (idx >> 5) & 3, l8 = idx & 31;
            int keep = ((mhalf * 4 + mf8loc) * 16 < C.mlim) ? 16 : 0;
            const __half* src = wsrc + ((size_t)((ks * 8 + mhalf * 4 + mf8loc) * 32 + l8)) * 8;
            cpa16_ca(As + idx * 16, src, keep);
        }
        const int cload = c_CHF[kt];
        if (cload >= 0) {
            const uint32_t hb = haloB + (cload & 1) * HALO_B;
            #pragma unroll
            for (int p = 0; p < 6; p++) {
                int u = tid + p * 256;
                if (u < 1360) {                 // 340 rows * 4 quads
                    int row = u >> 2, q = u & 3;
                    int hy = row / 34, hx = row - hy * 34;
                    int gy = py0 - 1 + hy, gx = px0 - 1 + hx;
                    bool ok = ((unsigned)gy < (unsigned)H) && ((unsigned)gx < (unsigned)W);
                    const __half* src = ok ? actL + (long long)(gy * W + gx) * 256 + cload * 32 + q * 8
                                           : actL;
                    cpa16(hb + row * 80 + q * 16, src, ok ? 16 : 0);
                }
            }
        }
        CP_COMMIT();
    };

    float acc[2][8][4];
    #pragma unroll
    for (int a = 0; a < 2; a++)
        #pragma unroll
        for (int b = 0; b < 8; b++)
            #pragma unroll
            for (int c = 0; c < 4; c++) acc[a][b][c] = 0.f;

    fill(0);
    fill(1);
    for (int kt = 0; kt < KT_N; kt++) {
        CP_WAIT1();
        __syncthreads();
        const int b32a = 2 * kt, b32b = b32a + 1;
        const int ca = b32a / 9, cb = b32b / 9;
        const int ta = b32a - ca * 9, tb = b32b - cb * 9;
        const int dA = ((ta / 3 - 1) * 34 + (ta - (ta / 3) * 3 - 1)) * 80;
        const int dB = ((tb / 3 - 1) * 34 + (tb - (tb / 3) * 3 - 1)) * 80;
        const uint32_t hA = haloB + (ca & 1) * HALO_B + dA;
        const uint32_t hB = haloB + (cb & 1) * HALO_B + dB;
        const __half* As = dsm + (kt % NSTAGE) * (A_STG_B / 2);

        auto do_ks = [&](int ks) {
            const uint32_t hsel = (ks >> 1) ? hB : hA;
            uint32_t bf[8][2];
            #pragma unroll
            for (int np = 0; np < 4; np++) {
                uint32_t addr = hsel + hbase[np] + (ks & 1) * 32;
                uint32_t r0, r1, r2, r3;
                asm volatile("ldmatrix.sync.aligned.m8n8.x4.shared.b16 {%0,%1,%2,%3}, [%4];"
                             : "=r"(r0), "=r"(r1), "=r"(r2), "=r"(r3)
                             : "r"(addr));
                bf[np*2][0] = r0; bf[np*2][1] = r1;
                bf[np*2+1][0] = r2; bf[np*2+1][1] = r3;
            }
            #pragma unroll
            for (int mf = 0; mf < 2; mf++) {
                if (warpM * 32 + mf * 16 >= C.mlim) continue;
                const uint4 av = *(const uint4*)(As + ((size_t)((ks * 4 + warpM * 2 + mf) * 32 + lane)) * 8);
                #pragma unroll
                for (int nf = 0; nf < 8; nf++) {
                    asm volatile(
                        "mma.sync.aligned.m16n8k16.row.col.f32.f16.f16.f32 "
                        "{%0,%1,%2,%3}, {%4,%5,%6,%7}, {%8,%9}, {%0,%1,%2,%3};"
                        : "+f"(acc[mf][nf][0]), "+f"(acc[mf][nf][1]),
                          "+f"(acc[mf][nf][2]), "+f"(acc[mf][nf][3])
                        : "r"(av.x), "r"(av.y), "r"(av.z), "r"(av.w),
                          "r"(bf[nf][0]), "r"(bf[nf][1]));
                }
            }
        };

        if (wact) do_ks(0);
        if (kt + 2 < KT_N) fill(kt + 2);
        if (wact) { do_ks(1); do_ks(2); do_ks(3); }
    }

    if (mblocks == 4) {
        // ---- staged coalesced epilogue (trunk: relu, half out) ----
        CP_WAIT0();
        __syncthreads();
        __half* stg = dsm;
        const float* bias = C.ba;
        #pragma unroll
        for (int mf = 0; mf < 2; mf++) {
            #pragma unroll
            for (int h = 0; h < 2; h++) {
                int ml = warpM * 32 + mf * 16 + (lane >> 2) + h * 8;
                float bv = bias[m0 + ml];
                #pragma unroll
                for (int nf = 0; nf < 8; nf++) {
                    #pragma unroll
                    for (int e = 0; e < 2; e++) {
                        int pl = warpN * 64 + nf * 8 + (lane & 3) * 2 + e;
                        float v = fmaxf(acc[mf][nf][h * 2 + e] + bv, 0.f);
                        stg[pl * MP2 + ml] = __float2half_rn(v);
                    }
                }
            }
        }
        __syncthreads();
        __half* outp = (__half*)C.oa;
        const int chunk = tid & 7;
        #pragma unroll
        for (int pass = 0; pass < 8; pass++) {
            int pl = pass * 32 + (tid >> 3);
            int py = py0 + (pl >> 5), px = px0 + (pl & 31);
            if (py < H && px < W) {
                uint4 v = *(const uint4*)(stg + pl * MP2 + chunk * 8);
                *(uint4*)(outp + (zco + py * W + px) * 256 + m0 + chunk * 8) = v;
            }
        }
    } else {
        // ---- legacy epilogue (heads: small M, float out) ----
        #pragma unroll
        for (int mf = 0; mf < 2; mf++) {
            #pragma unroll
            for (int h = 0; h < 2; h++) {
                int mg = m0 + warpM * 32 + mf * 16 + (lane >> 2) + h * 8;
                float bv = 0.f; void* op = 0; int st = 0, ac = 0, mo = 0;
                if (mg < C.msplit)    { bv = C.ba[mg];            op = C.oa; st = C.sa; ac = C.aa; mo = mg; }
                else if (mg < C.Mtot) { bv = C.bb[mg - C.msplit]; op = C.ob; st = C.sb; ac = C.ab; mo = mg - C.msplit; }
                if (!op) continue;
                #pragma unroll
                for (int nf = 0; nf < 8; nf++) {
                    #pragma unroll
                    for (int e = 0; e < 2; e++) {
                        int nl = warpN * 64 + nf * 8 + (lane & 3) * 2 + e;
                        int py = py0 + (nl >> 5), px = px0 + (nl & 31);
                        if (py >= H || px >= W) continue;
                        float v = acc[mf][nf][h * 2 + e] + bv;
                        if (ac == 1)      v = fmaxf(v, 0.f);
                        else if (ac == 2) v = 1.f / (1.f + expf(-v));
                        ((float*)op)[(zco + py * W + px) * (long long)st + mo] = v;
                    }
                }
            }
        }
    }
}

// ---------------- anchors / IoU ----------------
__device__ __forceinline__ void get_anchor(int a, float& x1, float& y1, float& x2, float& y2)
{
    int r = a % 3, cg = a / 3, lvl = 0;
    #pragma unroll
    for (int l = 1; l < 5; l++) if (cg >= c_CO[l]) lvl = l;
    int p = cg - c_CO[lvl], W = c_W[lvl];
    int y = p / W, x = p - y * W;
    float s = c_S[lvl];
    float wsr = (r==0) ? 4.f : (r==1) ? 3.f : 2.f;
    float hsr = (r==0) ? 4.f : 6.f;
    float hw = 0.5f * (wsr * s - 1.f), hh = 0.5f * (hsr * s - 1.f);
    x1 = 1.5f - hw + x * s;  x2 = 1.5f + hw + x * s;
    y1 = 1.5f - hh + y * s;  y2 = 1.5f + hh + y * s;
}
__device__ __forceinline__ float iou1(float ax1,float ay1,float ax2,float ay2,
                                      float bx1,float by1,float bx2,float by2)
{
    float aa = (ax2-ax1+1.f)*(ay2-ay1+1.f);
    float ab = (bx2-bx1+1.f)*(by2-by1+1.f);
    float iw = fmaxf(fminf(ax2,bx2)-fmaxf(ax1,bx1)+1.f, 0.f);
    float ih = fmaxf(fminf(ay2,by2)-fmaxf(ay1,by1)+1.f, 0.f);
    float inter = iw*ih;
    return inter / (aa + ab - inter);
}

__global__ void anchor_k(const float* __restrict__ gt,
                         const float* __restrict__ info, int n, int G)
{
    int idx = blockIdx.x * blockDim.x + threadIdx.x;
    if (idx >= n * NANCH) return;
    int b = idx / NANCH, a = idx - b * NANCH;
    float ax1,ay1,ax2,ay2; get_anchor(a, ax1,ay1,ax2,ay2);
    float aw = ax2-ax1+1.f, ah = ay2-ay1+1.f;
    float acx = ax1+0.5f*(aw-1.f), acy = ay1+0.5f*(ah-1.f);
    float cnt = info[b*6 + 5];
    const float* gb = gt + (long long)b * G * 5;

    float v1 = -1e30f, v2 = -1e30f; int i1 = 0, i2 = 0;
    for (int g = 0; g < G; g++) {
        float ov = -1.0f;
        if ((float)g < cnt && gb[g*5+4] != -1.0f)
            ov = iou1(ax1,ay1,ax2,ay2, gb[g*5+0],gb[g*5+1],gb[g*5+2],gb[g*5+3]);
        if (ov > v1)      { v2=v1; i2=i1; v1=ov; i1=g; }
        else if (ov > v2) { v2=ov; i2=g; }
    }
    long long base = (long long)idx * 2;
    g_lab[base+0] = (v1>=0.5f)?1.f:((v1<0.4f)?0.f:-1.f);
    g_lab[base+1] = (v2>=0.5f)?1.f:((v2<0.4f)?0.f:-1.f);
    int gi[2] = {i1, i2};
    #pragma unroll
    for (int k = 0; k < 2; k++) {
        const float* gg = gb + gi[k]*5;
        float gw = gg[2]-gg[0]+1.f, gh = gg[3]-gg[1]+1.f;
        float gcx = gg[0]+0.5f*(gw-1.f), gcy = gg[1]+0.5f*(gh-1.f);
        long long t = (base + k) * 4;
        g_tgt[t+0] = (gcx-acx)/aw;  g_tgt[t+1] = (gcy-acy)/ah;
        g_tgt[t+2] = logf(gw/aw);   g_tgt[t+3] = logf(gh/ah);
    }
}

__global__ void loss_k(const float* __restrict__ gt,
                       const float* __restrict__ info, int n, int G)
{
    __shared__ double sh[256];
    int idx = blockIdx.x * blockDim.x + threadIdx.x;
    double s_cls=0, s_bb=0, s_iou=0, s_num=0, c_pos=0, c_num=0;

    if (idx < n * NANCH) {
        int b = idx / NANCH, a = idx - b * NANCH;
        float ax1,ay1,ax2,ay2; get_anchor(a, ax1,ay1,ax2,ay2);
        float aw = ax2-ax1+1.f, ah = ay2-ay1+1.f;
        float acx = ax1+0.5f*(aw-1.f), acy = ay1+0.5f*(ah-1.f);
        float cnt = info[b*6 + 5];
        const float* gb = gt + (long long)b * G * 5;

        const float mxl = logf(62.5f);
        const float* o = g_off + (long long)idx * 8;
        float dt[2][4];
        #pragma unroll
        for (int k = 0; k < 2; k++) {
            float d0=o[k*4+0], d1=o[k*4+1], d2=o[k*4+2], d3=o[k*4+3];
            float pw = expf(fminf(d2, mxl)) * aw;
            float ph = expf(fminf(d3, mxl)) * ah;
            float pcx = d0*aw + acx, pcy = d1*ah + acy;
            dt[k][0] = pcx - 0.5f*(pw-1.f); dt[k][1] = pcy - 0.5f*(ph-1.f);
            dt[k][2] = pcx + 0.5f*(pw-1.f); dt[k][3] = pcy + 0.5f*(ph-1.f);
        }
        float best0 = -1e30f; int bi = 0;
        float m1 = -1e30f;    int mi1 = 0;
        float m2 = -1e30f;
        for (int g = 0; g < G; g++) {
            float keep = ((float)g < cnt && gb[g*5+4] != -1.0f) ? 1.f : 0.f;
            float ov0 = iou1(dt[0][0],dt[0][1],dt[0][2],dt[0][3],
                             gb[g*5+0],gb[g*5+1],gb[g*5+2],gb[g*5+3]) * keep;
            float ov1 = iou1(dt[1][0],dt[1][1],dt[1][2],dt[1][3],
                             gb[g*5+0],gb[g*5+1],gb[g*5+2],gb[g*5+3]) * keep;
            if (ov0 > best0) { best0 = ov0; bi = g; }
            if (ov1 > m1)      { m2 = m1; m1 = ov1; mi1 = g; }
            else if (ov1 > m2) { m2 = ov1; }
        }
        float iot[2];
        iot[0] = best0;
        iot[1] = (mi1 == bi) ? fmaxf(m2, 0.f) : m1;

        long long i2x = (long long)idx * 2;
        float la = g_lab[i2x], lb = g_lab[i2x+1];
        float ign = lb - ((la==0.f)?1.f:0.f) * ((lb!=0.f)?1.f:0.f);
        float L[2] = {la, ign};
        #pragma unroll
        for (int k = 0; k < 2; k++) {
            float Lk = L[k];
            float p  = g_cls[i2x+k];
            float mask   = (Lk != -1.f) ? 1.f : 0.f;
            float onehot = (Lk * mask == 1.f) ? 1.f : 0.f;
            float posv = (onehot != 0.f) ? (1.f-p)*(1.f-p)*logf(p) : 0.f;
            float negv = (onehot == 0.f) ? p*p*logf(1.f-p)         : 0.f;
            s_cls += (double)(-(0.25f*posv + 0.75f*negv) * mask);
            if (Lk > 0.f) {
                c_pos += 1.0;
                #pragma unroll
                for (int j = 0; j < 4; j++) {
                    float d  = o[k*4+j] - g_tgt[(i2x+k)*4 + j];
                    float ad = fabsf(d);
                    s_bb += (double)((ad < 1.f/9.f) ? 4.5f*d*d : ad - 0.5f/9.f);
                }
                s_iou += (double)fabsf(g_iouP[i2x+k] - iot[k]);
            }
        }
        int nl = ((L[0]>0.f)?1:0) + ((L[1]>0.f)?1:0) - 1;
        if (nl != -1) {
            float s0 = g_num[i2x], s1 = g_num[i2x+1];
            float m  = fmaxf(s0, s1);
            float lse = m + logf(expf(s0-m) + expf(s1-m));
            s_num += (double)(lse - ((nl==0) ? s0 : s1));
            c_num += 1.0;
        }
    }

    double vals[6] = {s_cls, s_bb, s_iou, s_num, c_pos, c_num};
    #pragma unroll
    for (int v = 0; v < 6; v++) {
        sh[threadIdx.x] = vals[v];
        __syncthreads();
        for (int st = 128; st > 0; st >>= 1) {
            if (threadIdx.x < st) sh[threadIdx.x] += sh[threadIdx.x + st];
            __syncthreads();
        }
        if (threadIdx.x == 0) atomicAdd(&g_acc[v], sh[0]);
        __syncthreads();
    }
}
__global__ void finalize_k(float* out)
{
    double np = fmax(g_acc[4], 1.0);
    double nn = fmax(g_acc[5], 1.0);
    out[0] = (float)(g_acc[0] / np);
    out[1] = (float)(2.0 * g_acc[1] / np);
    out[2] = (float)(2.0 * g_acc[2] / np);
    out[3] = (float)(g_acc[3] / nn);
}

// ---------------- launcher ----------------
extern "C" void kernel_launch(void* const* d_in, const int* in_sizes, int n_in,
                              void* d_out, int out_size)
{
    const float* f0 = (const float*)d_in[0];
    const float* f1 = (const float*)d_in[1];
    const float* f2 = (const float*)d_in[2];
    const float* f3 = (const float*)d_in[3];
    const float* f4 = (const float*)d_in[4];
    const float* gt      = (const float*)d_in[5];
    const float* info    = (const float*)d_in[6];
    const float* cls_w   = (const float*)d_in[7];
    const float* cls_b   = (const float*)d_in[8];
    const float* box_w   = (const float*)d_in[9];
    const float* box_b   = (const float*)d_in[10];
    const float* score_w = (const float*)d_in[11];
    const float* score_b = (const float*)d_in[12];
    const float* bpred_w = (const float*)d_in[13];
    const float* bpred_b = (const float*)d_in[14];
    const float* iou_w   = (const float*)d_in[15];
    const float* iou_b   = (const float*)d_in[16];
    const float* num_w   = (const float*)d_in[17];
    const float* num_b   = (const float*)d_in[18];

    int n = in_sizes[6] / 6;
    if (n < 1) n = 1; if (n > NB) n = NB;
    int G = in_sizes[5] / (n * 5);

    __half *aI, *ac0, *ac1, *ab0, *ab1;
    float *pc, *pn, *pi, *po;
    cudaGetSymbolAddress((void**)&aI,  g_actI);
    cudaGetSymbolAddress((void**)&ac0, g_c0);
    cudaGetSymbolAddress((void**)&ac1, g_c1);
    cudaGetSymbolAddress((void**)&ab0, g_b0);
    cudaGetSymbolAddress((void**)&ab1, g_b1);
    cudaGetSymbolAddress((void**)&pc,  g_cls);
    cudaGetSymbolAddress((void**)&pn,  g_num);
    cudaGetSymbolAddress((void**)&pi,  g_iouP);
    cudaGetSymbolAddress((void**)&po,  g_off);

    const int DSM = DSM_B;   // 78976 bytes

    static cudaStream_t s1 = 0, s2 = 0;
    static cudaEvent_t  evF = 0, ev1 = 0, ev2 = 0, evW = 0, evI = 0;
    if (!s1) {
        cudaFuncSetAttribute(conv_mma, cudaFuncAttributeMaxDynamicSharedMemorySize, DSM);
        cudaStreamCreateWithFlags(&s1, cudaStreamNonBlocking);
        cudaStreamCreateWithFlags(&s2, cudaStreamNonBlocking);
        cudaEventCreateWithFlags(&evF, cudaEventDisableTiming);
        cudaEventCreateWithFlags(&ev1, cudaEventDisableTiming);
        cudaEventCreateWithFlags(&ev2, cudaEventDisableTiming);
        cudaEventCreateWithFlags(&evW, cudaEventDisableTiming);
        cudaEventCreateWithFlags(&evI, cudaEventDisableTiming);
    }

    cudaEventRecord(evF, 0);
    cudaStreamWaitEvent(s1, evF, 0);
    cudaStreamWaitEvent(s2, evF, 0);

    transpose_w_k<<<(WA_TOT + 255) / 256, 256, 0, s1>>>(cls_w, box_w, score_w, num_w, bpred_w, iou_w);
    transpose_in_k<<<dim3(640, 8, n), dim3(32, 8), 0, s2>>>(f0, f1, f2, f3, f4);
    cudaEventRecord(evW, s1);
    cudaEventRecord(evI, s2);
    cudaStreamWaitEvent(s1, evI, 0);
    cudaStreamWaitEvent(s2, evW, 0);

    int tot = n * NANCH;
    int gb  = (tot + 255) / 256;
    anchor_k<<<gb, 256>>>(gt, info, n, G);

    dim3 blk(256);
    dim3 gridB(NPATCH, 4, n);
    dim3 gridH(NPATCH, 1, n);

    const __half* cin[4] = {aI, ac0, ac1, ac0};
    const __half* bin[4] = {aI, ab0, ab1, ab0};
    __half* cout[4] = {ac0, ac1, ac0, ac1};
    __half* bout[4] = {ab0, ab1, ab0, ab1};
    for (int i = 0; i < 4; i++) {
        BCfg cc = { cin[i], i*2,   cls_b + i*256, cls_b + i*256, 256,
                    cout[i], cout[i], 256, 256, 1, 1, 256, 1, 128 };
        conv_mma<<<gridB, blk, DSM, s1>>>(cc, cc, 4);
        BCfg cb = { bin[i], 8+i*2, box_b + i*256, box_b + i*256, 256,
                    bout[i], bout[i], 256, 256, 1, 1, 256, 1, 128 };
        conv_mma<<<gridB, blk, DSM, s2>>>(cb, cb, 4);
    }
    {
        BCfg hc = { ac1, 16, score_b, num_b, 6,  pc, pn, 6,  6, 2, 0, 12, 0, 32 };
        conv_mma<<<gridH, blk, DSM, s1>>>(hc, hc, 1);
        BCfg hb = { ab1, 17, bpred_b, iou_b, 24, po, pi, 24, 6, 0, 0, 30, 0, 32 };
        conv_mma<<<gridH, blk, DSM, s2>>>(hb, hb, 1);
    }

    cudaEventRecord(ev1, s1);
    cudaEventRecord(ev2, s2);
    cudaStreamWaitEvent(0, ev1, 0);
    cudaStreamWaitEvent(0, ev2, 0);

    loss_k<<<gb, 256>>>(gt, info, n, G);
    finalize_k<<<1, 1>>>((float*)d_out);
}

// round 16
// speedup vs baseline: 1.0546x; 1.0546x over previous
#include <cuda_runtime.h>
#include <cuda_fp16.h>
#include <math.h>
#include <stdint.h>

// ---------------- problem constants ----------------
#define NB      2
#define CIN     256
#define KTOT    2304
#define TOTCELL 20460
#define NANCH   (TOTCELL*3)
#define TRUNK_SZ 589824
#define KT_N     36
#define WA_BLOB  8192                      // halves per (block, ktile)
#define WA_BLK   (KT_N*WA_BLOB)
#define WA_TOT   (18*WA_BLK)
#define NSTAGE   4
#define A_STG_B  16384                     // bytes per A stage
#define HALO_B   14400                     // bytes per halo chunk buffer (180 rows * 80B)
#define HALO_OFF (NSTAGE*A_STG_B)          // 65536
#define DSM_B    (HALO_OFF + 2*HALO_B)     // 94336 bytes
#define MP       136                       // epilogue staging row stride (halves)
#define NPATCH   164

__constant__ int   c_H[5]    = {6,12,24,48,96};
__constant__ int   c_W[5]    = {10,20,40,80,160};
__constant__ int   c_HW[5]   = {60,240,960,3840,15360};
__constant__ int   c_CO[5]   = {0,60,300,1260,5100};
__constant__ int   c_PTC[5]  = {0,1,5,14,44};    // patch tile offsets (164 total)
__constant__ int   c_PCOL[5] = {1,2,3,5,10};     // patches along x
__constant__ int   c_PT[5]   = {0,2,10,40,160};  // 32-pos tile offsets (input transpose)
__constant__ float c_S[5]    = {128.f,64.f,32.f,16.f,8.f};
// chunk-load schedule for NSTAGE=4 / wait_group 2 (fill stage s -> chunk id or -1)
__constant__ int   c_CHF[36] = {0,1,-1,-1,-1,-1,-1,-1,2,-1,-1,-1,3,-1,-1,-1,-1,4,-1,-1,
                                -1,5,-1,-1,-1,-1,6,-1,-1,-1,7,-1,-1,-1,-1,-1};

// ---------------- device scratch ----------------
__device__ __align__(16) __half g_wA[WA_TOT];
__device__ __align__(16) __half g_actI[NB*TOTCELL*CIN];
__device__ __align__(16) __half g_c0[NB*TOTCELL*CIN];
__device__ __align__(16) __half g_c1[NB*TOTCELL*CIN];
__device__ __align__(16) __half g_b0[NB*TOTCELL*CIN];
__device__ __align__(16) __half g_b1[NB*TOTCELL*CIN];
__device__ float  g_cls [NB*NANCH*2];
__device__ float  g_num [NB*NANCH*2];
__device__ float  g_iouP[NB*NANCH*2];
__device__ float  g_off [NB*NANCH*8];
__device__ float  g_lab [NB*NANCH*2];
__device__ float  g_tgt [NB*NANCH*8];
__device__ double g_acc[6];

// ---------------- helpers ----------------
__device__ __forceinline__ uint32_t smem_u32(const void* p) {
    uint32_t a;
    asm("{ .reg .u64 t; cvta.to.shared.u64 t, %1; cvt.u32.u64 %0, t; }" : "=r"(a) : "l"(p));
    return a;
}
__device__ __forceinline__ void cpa16(uint32_t dst, const void* src, int sz) {
    asm volatile("cp.async.cg.shared.global [%0], [%1], 16, %2;"
                 :: "r"(dst), "l"(src), "r"(sz) : "memory");
}
__device__ __forceinline__ void cpa16_ca(uint32_t dst, const void* src, int sz) {
    asm volatile("cp.async.ca.shared.global [%0], [%1], 16, %2;"
                 :: "r"(dst), "l"(src), "r"(sz) : "memory");
}
#define CP_COMMIT() asm volatile("cp.async.commit_group;" ::: "memory")
#define CP_WAIT2()  asm volatile("cp.async.wait_group 2;"  ::: "memory")
#define CP_WAIT0()  asm volatile("cp.async.wait_group 0;"  ::: "memory")

// ---------- weight transpose into m16n8k16 A-fragment order (fp16) --------
__global__ void transpose_w_k(const float* __restrict__ cls_w, const float* __restrict__ box_w,
                              const float* __restrict__ score_w, const float* __restrict__ num_w,
                              const float* __restrict__ bpred_w, const float* __restrict__ iou_w)
{
    if (blockIdx.x == 0 && threadIdx.x < 6) g_acc[threadIdx.x] = 0.0;
    int i = blockIdx.x * 256 + threadIdx.x;
    if (i >= WA_TOT) return;
    int blk = i / WA_BLK;
    int rem = i - blk * WA_BLK;
    int kt  = rem / WA_BLOB;
    int r2  = rem - kt * WA_BLOB;
    int ks   = r2 >> 11;
    int mf8  = (r2 >> 8) & 7;
    int lane = (r2 >> 3) & 31;
    int h    = r2 & 7;
    int m  = mf8 * 16 + (lane >> 2) + ((h >> 1) & 1) * 8;
    int kl = ks * 16 + (lane & 3) * 2 + (h & 1) + ((h >> 2) & 1) * 8;
    int kp = kt * 64 + kl;
    int kb = kp >> 5, ci = kp & 31;
    int chunk = kb / 9, tap = kb - chunk * 9;
    int korig = (chunk * 32 + ci) * 9 + tap;

    float v = 0.f;
    if (blk < 16) {
        int L = blk >> 1; int mrow = (blk & 1) * 128 + m;
        const float* base = (L < 4) ? cls_w + (long long)L * TRUNK_SZ
                                    : box_w + (long long)(L - 4) * TRUNK_SZ;
        v = base[(long long)mrow * KTOT + korig];
    } else if (blk == 16) {
        if (m < 6)       v = score_w[(long long)m * KTOT + korig];
        else if (m < 12) v = num_w[(long long)(m - 6) * KTOT + korig];
    } else {
        if (m < 24)      v = bpred_w[(long long)m * KTOT + korig];
        else if (m < 30) v = iou_w[(long long)(m - 24) * KTOT + korig];
    }
    g_wA[i] = __float2half_rn(v);
}

// ---------- input transpose ----------
__global__ void transpose_in_k(const float* __restrict__ f0, const float* __restrict__ f1,
                               const float* __restrict__ f2, const float* __restrict__ f3,
                               const float* __restrict__ f4)
{
    __shared__ float tile[32][33];
    int bx = blockIdx.x, lvl = 0;
    #pragma unroll
    for (int l = 1; l < 5; l++) if (bx >= c_PT[l]) lvl = l;
    const int HW = c_HW[lvl];
    const int p0 = (bx - c_PT[lvl]) * 32;
    const int c0 = blockIdx.y * 32;
    const int z  = blockIdx.z;
    const float* src = (lvl==0?f0:lvl==1?f1:lvl==2?f2:lvl==3?f3:f4) + (long long)z*256*HW;
    int tx = threadIdx.x, ty = threadIdx.y;
    for (int r = ty; r < 32; r += 8) {
        int p = p0 + tx;
        tile[r][tx] = (p < HW) ? src[(long long)(c0 + r) * HW + p] : 0.f;
    }
    __syncthreads();
    __half* dst = g_actI + ((long long)z * TOTCELL + c_CO[lvl]) * 256;
    for (int j = ty; j < 32; j += 8) {
        int p = p0 + j;
        if (p < HW) dst[(long long)p * 256 + c0 + tx] = __float2half_rn(tile[tx][j]);
    }
}

// ---------- per-branch config ----------
struct BCfg {
    const __half* in;
    int wblk;
    const float* ba; const float* bb;
    int msplit;
    void* oa; void* ob;
    int sa, sb, aa, ab, Mtot, outHalf, mlim;
};

// ---------- fp16 mma.sync conv, halo-tile B: CTA 128(M) x 8x16 patch ------
__global__ void __launch_bounds__(256, 2) conv_mma(BCfg c0, BCfg c1, int mblocks)
{
    extern __shared__ __align__(16) __half dsm[];
    const uint32_t sm0  = smem_u32(dsm);
    const uint32_t haloB = sm0 + HALO_OFF;
    const int tid  = threadIdx.x;
    const int lane = tid & 31;
    const int wid  = tid >> 5;
    const int warpM = wid & 1;
    const int warpN = wid >> 1;

    const int yb = blockIdx.y;
    const int mb = (mblocks == 2) ? (yb & 1) : 0;
    const BCfg& C = ((mblocks == 2 ? (yb >> 1) : yb) ? c1 : c0);

    int bx = blockIdx.x, lvl = 0;
    #pragma unroll
    for (int l = 1; l < 5; l++) if (bx >= c_PTC[l]) lvl = l;
    const int H = c_H[lvl], W = c_W[lvl];
    const int pidx = bx - c_PTC[lvl];
    const int pcw  = c_PCOL[lvl];
    const int prow = pidx / pcw;
    const int py0  = prow * 8;
    const int px0  = (pidx - prow * pcw) * 16;
    const int m0 = mb * 128;
    const int z  = blockIdx.z;
    const long long zco = (long long)z * TOTCELL + c_CO[lvl];
    const __half* actL = C.in + zco * 256;
    const __half* wA = g_wA + (size_t)(C.wblk + mb) * WA_BLK;
    const int mf8lim = C.mlim >> 4;
    const bool wact = (warpM * 64) < C.mlim;

    // per-thread ldmatrix row bases (bytes into a halo buffer, tap-independent)
    const int gq = lane >> 3, rr = lane & 7;
    int hbase[2];
    #pragma unroll
    for (int np = 0; np < 2; np++) {
        int nn = warpN * 32 + (np * 2 + (gq >> 1)) * 8 + rr;
        hbase[np] = (((nn >> 4) + 1) * 18 + ((nn & 15) + 1)) * 80 + (gq & 1) * 16;
    }

    auto fill = [&](int kt) {
        const uint32_t As = sm0 + (kt % NSTAGE) * A_STG_B;
        const __half* wsrc = wA + (size_t)kt * WA_BLOB;
        #pragma unroll
        for (int i = 0; i < 4; i++) {
            int idx8 = i * 256 + tid;
            int keep = (((idx8 >> 5) & 7) < mf8lim) ? 16 : 0;
            cpa16_ca(As + idx8 * 16, wsrc + idx8 * 8, keep);
        }
        const int cload = c_CHF[kt];
        if (cload >= 0) {
            const uint32_t hb = haloB + (cload & 1) * HALO_B;
            #pragma unroll
            for (int p = 0; p < 3; p++) {
                int u = tid + p * 256;
                if (u < 720) {
                    int row = u >> 2, q = u & 3;
                    int hy = row / 18, hx = row - hy * 18;
                    int gy = py0 - 1 + hy, gx = px0 - 1 + hx;
                    bool ok = ((unsigned)gy < (unsigned)H) && ((unsigned)gx < (unsigned)W);
                    const __half* src = ok ? actL + (long long)(gy * W + gx) * 256 + cload * 32 + q * 8
                                           : actL;
                    cpa16(hb + row * 80 + q * 16, src, ok ? 16 : 0);
                }
            }
        }
        CP_COMMIT();
    };

    float acc[4][4][4];
    #pragma unroll
    for (int a = 0; a < 4; a++)
        #pragma unroll
        for (int b = 0; b < 4; b++)
            #pragma unroll
            for (int c = 0; c < 4; c++) acc[a][b][c] = 0.f;

    fill(0);
    fill(1);
    fill(2);
    for (int kt = 0; kt < KT_N; kt++) {
        CP_WAIT2();
        __syncthreads();
        const int b32a = 2 * kt, b32b = b32a + 1;
        const int ca = b32a / 9, cb = b32b / 9;
        const int ta = b32a - ca * 9, tb = b32b - cb * 9;
        const int dA = ((ta / 3 - 1) * 18 + (ta - (ta / 3) * 3 - 1)) * 80;
        const int dB = ((tb / 3 - 1) * 18 + (tb - (tb / 3) * 3 - 1)) * 80;
        const uint32_t hA = haloB + (ca & 1) * HALO_B + dA;
        const uint32_t hB = haloB + (cb & 1) * HALO_B + dB;
        const __half* As = dsm + (kt % NSTAGE) * (A_STG_B / 2);

        auto do_ks = [&](int ks) {
            const uint32_t hsel = (ks >> 1) ? hB : hA;
            uint32_t bf[4][2];
            #pragma unroll
            for (int np = 0; np < 2; np++) {
                uint32_t addr = hsel + hbase[np] + (ks & 1) * 32;
                uint32_t r0, r1, r2, r3;
                asm volatile("ldmatrix.sync.aligned.m8n8.x4.shared.b16 {%0,%1,%2,%3}, [%4];"
                             : "=r"(r0), "=r"(r1), "=r"(r2), "=r"(r3)
                             : "r"(addr));
                bf[np*2][0] = r0; bf[np*2][1] = r1;
                bf[np*2+1][0] = r2; bf[np*2+1][1] = r3;
            }
            #pragma unroll
            for (int mf = 0; mf < 4; mf++) {
                if (warpM * 64 + mf * 16 >= C.mlim) continue;
                const uint4 av = *(const uint4*)(As + ((size_t)((ks * 8 + warpM * 4 + mf) * 32 + lane)) * 8);
                #pragma unroll
                for (int nf = 0; nf < 4; nf++) {
                    asm volatile(
                        "mma.sync.aligned.m16n8k16.row.col.f32.f16.f16.f32 "
                        "{%0,%1,%2,%3}, {%4,%5,%6,%7}, {%8,%9}, {%0,%1,%2,%3};"
                        : "+f"(acc[mf][nf][0]), "+f"(acc[mf][nf][1]),
                          "+f"(acc[mf][nf][2]), "+f"(acc[mf][nf][3])
                        : "r"(av.x), "r"(av.y), "r"(av.z), "r"(av.w),
                          "r"(bf[nf][0]), "r"(bf[nf][1]));
                }
            }
        };

        if (wact) do_ks(0);
        if (kt + 3 < KT_N) fill(kt + 3);
        if (wact) { do_ks(1); do_ks(2); do_ks(3); }
    }

    if (mblocks == 2) {
        // ---- staged coalesced epilogue (trunk: relu, half out) ----
        CP_WAIT0();
        __syncthreads();
        __half* stg = dsm;
        const float* bias = C.ba;
        #pragma unroll
        for (int mf = 0; mf < 4; mf++) {
            #pragma unroll
            for (int h = 0; h < 2; h++) {
                int ml = warpM * 64 + mf * 16 + (lane >> 2) + h * 8;
                float bv = bias[m0 + ml];
                #pragma unroll
                for (int nf = 0; nf < 4; nf++) {
                    #pragma unroll
                    for (int e = 0; e < 2; e++) {
                        int pl = warpN * 32 + nf * 8 + (lane & 3) * 2 + e;
                        float v = fmaxf(acc[mf][nf][h * 2 + e] + bv, 0.f);
                        stg[pl * MP + ml] = __float2half_rn(v);
                    }
                }
            }
        }
        __syncthreads();
        __half* outp = (__half*)C.oa;
        const int chunk = tid & 15;
        #pragma unroll
        for (int pass = 0; pass < 8; pass++) {
            int pl = pass * 16 + (tid >> 4);
            int py = py0 + (pl >> 4), px = px0 + (pl & 15);
            if (py < H && px < W) {
                uint4 v = *(const uint4*)(stg + pl * MP + chunk * 8);
                *(uint4*)(outp + (zco + py * W + px) * 256 + m0 + chunk * 8) = v;
            }
        }
    } else {
        // ---- legacy epilogue (heads: small M, float out) ----
        #pragma unroll
        for (int mf = 0; mf < 4; mf++) {
            #pragma unroll
            for (int h = 0; h < 2; h++) {
                int mg = m0 + warpM * 64 + mf * 16 + (lane >> 2) + h * 8;
                float bv = 0.f; void* op = 0; int st = 0, ac = 0, mo = 0;
                if (mg < C.msplit)    { bv = C.ba[mg];            op = C.oa; st = C.sa; ac = C.aa; mo = mg; }
                else if (mg < C.Mtot) { bv = C.bb[mg - C.msplit]; op = C.ob; st = C.sb; ac = C.ab; mo = mg - C.msplit; }
                if (!op) continue;
                #pragma unroll
                for (int nf = 0; nf < 4; nf++) {
                    #pragma unroll
                    for (int e = 0; e < 2; e++) {
                        int nl = warpN * 32 + nf * 8 + (lane & 3) * 2 + e;
                        int py = py0 + (nl >> 4), px = px0 + (nl & 15);
                        if (py >= H || px >= W) continue;
                        float v = acc[mf][nf][h * 2 + e] + bv;
                        if (ac == 1)      v = fmaxf(v, 0.f);
                        else if (ac == 2) v = 1.f / (1.f + expf(-v));
                        ((float*)op)[(zco + py * W + px) * (long long)st + mo] = v;
                    }
                }
            }
        }
    }
}

// ---------------- anchors / IoU ----------------
__device__ __forceinline__ void get_anchor(int a, float& x1, float& y1, float& x2, float& y2)
{
    int r = a % 3, cg = a / 3, lvl = 0;
    #pragma unroll
    for (int l = 1; l < 5; l++) if (cg >= c_CO[l]) lvl = l;
    int p = cg - c_CO[lvl], W = c_W[lvl];
    int y = p / W, x = p - y * W;
    float s = c_S[lvl];
    float wsr = (r==0) ? 4.f : (r==1) ? 3.f : 2.f;
    float hsr = (r==0) ? 4.f : 6.f;
    float hw = 0.5f * (wsr * s - 1.f), hh = 0.5f * (hsr * s - 1.f);
    x1 = 1.5f - hw + x * s;  x2 = 1.5f + hw + x * s;
    y1 = 1.5f - hh + y * s;  y2 = 1.5f + hh + y * s;
}
__device__ __forceinline__ float iou1(float ax1,float ay1,float ax2,float ay2,
                                      float bx1,float by1,float bx2,float by2)
{
    float aa = (ax2-ax1+1.f)*(ay2-ay1+1.f);
    float ab = (bx2-bx1+1.f)*(by2-by1+1.f);
    float iw = fmaxf(fminf(ax2,bx2)-fmaxf(ax1,bx1)+1.f, 0.f);
    float ih = fmaxf(fminf(ay2,by2)-fmaxf(ay1,by1)+1.f, 0.f);
    float inter = iw*ih;
    return inter / (aa + ab - inter);
}

__global__ void anchor_k(const float* __restrict__ gt,
                         const float* __restrict__ info, int n, int G)
{
    int idx = blockIdx.x * blockDim.x + threadIdx.x;
    if (idx >= n * NANCH) return;
    int b = idx / NANCH, a = idx - b * NANCH;
    float ax1,ay1,ax2,ay2; get_anchor(a, ax1,ay1,ax2,ay2);
    float aw = ax2-ax1+1.f, ah = ay2-ay1+1.f;
    float acx = ax1+0.5f*(aw-1.f), acy = ay1+0.5f*(ah-1.f);
    float cnt = info[b*6 + 5];
    const float* gb = gt + (long long)b * G * 5;

    float v1 = -1e30f, v2 = -1e30f; int i1 = 0, i2 = 0;
    for (int g = 0; g < G; g++) {
        float ov = -1.0f;
        if ((float)g < cnt && gb[g*5+4] != -1.0f)
            ov = iou1(ax1,ay1,ax2,ay2, gb[g*5+0],gb[g*5+1],gb[g*5+2],gb[g*5+3]);
        if (ov > v1)      { v2=v1; i2=i1; v1=ov; i1=g; }
        else if (ov > v2) { v2=ov; i2=g; }
    }
    long long base = (long long)idx * 2;
    g_lab[base+0] = (v1>=0.5f)?1.f:((v1<0.4f)?0.f:-1.f);
    g_lab[base+1] = (v2>=0.5f)?1.f:((v2<0.4f)?0.f:-1.f);
    int gi[2] = {i1, i2};
    #pragma unroll
    for (int k = 0; k < 2; k++) {
        const float* gg = gb + gi[k]*5;
        float gw = gg[2]-gg[0]+1.f, gh = gg[3]-gg[1]+1.f;
        float gcx = gg[0]+0.5f*(gw-1.f), gcy = gg[1]+0.5f*(gh-1.f);
        long long t = (base + k) * 4;
        g_tgt[t+0] = (gcx-acx)/aw;  g_tgt[t+1] = (gcy-acy)/ah;
        g_tgt[t+2] = logf(gw/aw);   g_tgt[t+3] = logf(gh/ah);
    }
}

__global__ void loss_k(const float* __restrict__ gt,
                       const float* __restrict__ info, int n, int G)
{
    __shared__ double sh[256];
    int idx = blockIdx.x * blockDim.x + threadIdx.x;
    double s_cls=0, s_bb=0, s_iou=0, s_num=0, c_pos=0, c_num=0;

    if (idx < n * NANCH) {
        int b = idx / NANCH, a = idx - b * NANCH;
        float ax1,ay1,ax2,ay2; get_anchor(a, ax1,ay1,ax2,ay2);
        float aw = ax2-ax1+1.f, ah = ay2-ay1+1.f;
        float acx = ax1+0.5f*(aw-1.f), acy = ay1+0.5f*(ah-1.f);
        float cnt = info[b*6 + 5];
        const float* gb = gt + (long long)b * G * 5;

        const float mxl = logf(62.5f);
        const float* o = g_off + (long long)idx * 8;
        float dt[2][4];
        #pragma unroll
        for (int k = 0; k < 2; k++) {
            float d0=o[k*4+0], d1=o[k*4+1], d2=o[k*4+2], d3=o[k*4+3];
            float pw = expf(fminf(d2, mxl)) * aw;
            float ph = expf(fminf(d3, mxl)) * ah;
            float pcx = d0*aw + acx, pcy = d1*ah + acy;
            dt[k][0] = pcx - 0.5f*(pw-1.f); dt[k][1] = pcy - 0.5f*(ph-1.f);
            dt[k][2] = pcx + 0.5f*(pw-1.f); dt[k][3] = pcy + 0.5f*(ph-1.f);
        }
        float best0 = -1e30f; int bi = 0;
        float m1 = -1e30f;    int mi1 = 0;
        float m2 = -1e30f;
        for (int g = 0; g < G; g++) {
            float keep = ((float)g < cnt && gb[g*5+4] != -1.0f) ? 1.f : 0.f;
            float ov0 = iou1(dt[0][0],dt[0][1],dt[0][2],dt[0][3],
                             gb[g*5+0],gb[g*5+1],gb[g*5+2],gb[g*5+3]) * keep;
            float ov1 = iou1(dt[1][0],dt[1][1],dt[1][2],dt[1][3],
                             gb[g*5+0],gb[g*5+1],gb[g*5+2],gb[g*5+3]) * keep;
            if (ov0 > best0) { best0 = ov0; bi = g; }
            if (ov1 > m1)      { m2 = m1; m1 = ov1; mi1 = g; }
            else if (ov1 > m2) { m2 = ov1; }
        }
        float iot[2];
        iot[0] = best0;
        iot[1] = (mi1 == bi) ? fmaxf(m2, 0.f) : m1;

        long long i2x = (long long)idx * 2;
        float la = g_lab[i2x], lb = g_lab[i2x+1];
        float ign = lb - ((la==0.f)?1.f:0.f) * ((lb!=0.f)?1.f:0.f);
        float L[2] = {la, ign};
        #pragma unroll
        for (int k = 0; k < 2; k++) {
            float Lk = L[k];
            float p  = g_cls[i2x+k];
            float mask   = (Lk != -1.f) ? 1.f : 0.f;
            float onehot = (Lk * mask == 1.f) ? 1.f : 0.f;
            float posv = (onehot != 0.f) ? (1.f-p)*(1.f-p)*logf(p) : 0.f;
            float negv = (onehot == 0.f) ? p*p*logf(1.f-p)         : 0.f;
            s_cls += (double)(-(0.25f*posv + 0.75f*negv) * mask);
            if (Lk > 0.f) {
                c_pos += 1.0;
                #pragma unroll
                for (int j = 0; j < 4; j++) {
                    float d  = o[k*4+j] - g_tgt[(i2x+k)*4 + j];
                    float ad = fabsf(d);
                    s_bb += (double)((ad < 1.f/9.f) ? 4.5f*d*d : ad - 0.5f/9.f);
                }
                s_iou += (double)fabsf(g_iouP[i2x+k] - iot[k]);
            }
        }
        int nl = ((L[0]>0.f)?1:0) + ((L[1]>0.f)?1:0) - 1;
        if (nl != -1) {
            float s0 = g_num[i2x], s1 = g_num[i2x+1];
            float m  = fmaxf(s0, s1);
            float lse = m + logf(expf(s0-m) + expf(s1-m));
            s_num += (double)(lse - ((nl==0) ? s0 : s1));
            c_num += 1.0;
        }
    }

    double vals[6] = {s_cls, s_bb, s_iou, s_num, c_pos, c_num};
    #pragma unroll
    for (int v = 0; v < 6; v++) {
        sh[threadIdx.x] = vals[v];
        __syncthreads();
        for (int st = 128; st > 0; st >>= 1) {
            if (threadIdx.x < st) sh[threadIdx.x] += sh[threadIdx.x + st];
            __syncthreads();
        }
        if (threadIdx.x == 0) atomicAdd(&g_acc[v], sh[0]);
        __syncthreads();
    }
}
__global__ void finalize_k(float* out)
{
    double np = fmax(g_acc[4], 1.0);
    double nn = fmax(g_acc[5], 1.0);
    out[0] = (float)(g_acc[0] / np);
    out[1] = (float)(2.0 * g_acc[1] / np);
    out[2] = (float)(2.0 * g_acc[2] / np);
    out[3] = (float)(g_acc[3] / nn);
}

// ---------------- launcher ----------------
extern "C" void kernel_launch(void* const* d_in, const int* in_sizes, int n_in,
                              void* d_out, int out_size)
{
    const float* f0 = (const float*)d_in[0];
    const float* f1 = (const float*)d_in[1];
    const float* f2 = (const float*)d_in[2];
    const float* f3 = (const float*)d_in[3];
    const float* f4 = (const float*)d_in[4];
    const float* gt      = (const float*)d_in[5];
    const float* info    = (const float*)d_in[6];
    const float* cls_w   = (const float*)d_in[7];
    const float* cls_b   = (const float*)d_in[8];
    const float* box_w   = (const float*)d_in[9];
    const float* box_b   = (const float*)d_in[10];
    const float* score_w = (const float*)d_in[11];
    const float* score_b = (const float*)d_in[12];
    const float* bpred_w = (const float*)d_in[13];
    const float* bpred_b = (const float*)d_in[14];
    const float* iou_w   = (const float*)d_in[15];
    const float* iou_b   = (const float*)d_in[16];
    const float* num_w   = (const float*)d_in[17];
    const float* num_b   = (const float*)d_in[18];

    int n = in_sizes[6] / 6;
    if (n < 1) n = 1; if (n > NB) n = NB;
    int G = in_sizes[5] / (n * 5);

    __half *aI, *ac0, *ac1, *ab0, *ab1;
    float *pc, *pn, *pi, *po;
    cudaGetSymbolAddress((void**)&aI,  g_actI);
    cudaGetSymbolAddress((void**)&ac0, g_c0);
    cudaGetSymbolAddress((void**)&ac1, g_c1);
    cudaGetSymbolAddress((void**)&ab0, g_b0);
    cudaGetSymbolAddress((void**)&ab1, g_b1);
    cudaGetSymbolAddress((void**)&pc,  g_cls);
    cudaGetSymbolAddress((void**)&pn,  g_num);
    cudaGetSymbolAddress((void**)&pi,  g_iouP);
    cudaGetSymbolAddress((void**)&po,  g_off);

    const int DSM = DSM_B;   // 94336 bytes

    static cudaStream_t s1 = 0, s2 = 0;
    static cudaEvent_t  evF = 0, ev1 = 0, ev2 = 0, evW = 0, evI = 0;
    if (!s1) {
        cudaFuncSetAttribute(conv_mma, cudaFuncAttributeMaxDynamicSharedMemorySize, DSM);
        cudaStreamCreateWithFlags(&s1, cudaStreamNonBlocking);
        cudaStreamCreateWithFlags(&s2, cudaStreamNonBlocking);
        cudaEventCreateWithFlags(&evF, cudaEventDisableTiming);
        cudaEventCreateWithFlags(&ev1, cudaEventDisableTiming);
        cudaEventCreateWithFlags(&ev2, cudaEventDisableTiming);
        cudaEventCreateWithFlags(&evW, cudaEventDisableTiming);
        cudaEventCreateWithFlags(&evI, cudaEventDisableTiming);
    }

    cudaEventRecord(evF, 0);
    cudaStreamWaitEvent(s1, evF, 0);
    cudaStreamWaitEvent(s2, evF, 0);

    transpose_w_k<<<(WA_TOT + 255) / 256, 256, 0, s1>>>(cls_w, box_w, score_w, num_w, bpred_w, iou_w);
    transpose_in_k<<<dim3(640, 8, n), dim3(32, 8), 0, s2>>>(f0, f1, f2, f3, f4);
    cudaEventRecord(evW, s1);
    cudaEventRecord(evI, s2);
    cudaStreamWaitEvent(s1, evI, 0);
    cudaStreamWaitEvent(s2, evW, 0);

    int tot = n * NANCH;
    int gb  = (tot + 255) / 256;
    anchor_k<<<gb, 256>>>(gt, info, n, G);

    dim3 blk(256);
    dim3 gridB(NPATCH, 2, n);
    dim3 gridH(NPATCH, 1, n);

    const __half* cin[4] = {aI, ac0, ac1, ac0};
    const __half* bin[4] = {aI, ab0, ab1, ab0};
    __half* cout[4] = {ac0, ac1, ac0, ac1};
    __half* bout[4] = {ab0, ab1, ab0, ab1};
    for (int i = 0; i < 4; i++) {
        BCfg cc = { cin[i], i*2,   cls_b + i*256, cls_b + i*256, 256,
                    cout[i], cout[i], 256, 256, 1, 1, 256, 1, 128 };
        conv_mma<<<gridB, blk, DSM, s1>>>(cc, cc, 2);
        BCfg cb = { bin[i], 8+i*2, box_b + i*256, box_b + i*256, 256,
                    bout[i], bout[i], 256, 256, 1, 1, 256, 1, 128 };
        conv_mma<<<gridB, blk, DSM, s2>>>(cb, cb, 2);
    }
    {
        BCfg hc = { ac1, 16, score_b, num_b, 6,  pc, pn, 6,  6, 2, 0, 12, 0, 32 };
        conv_mma<<<gridH, blk, DSM, s1>>>(hc, hc, 1);
        BCfg hb = { ab1, 17, bpred_b, iou_b, 24, po, pi, 24, 6, 0, 0, 30, 0, 32 };
        conv_mma<<<gridH, blk, DSM, s2>>>(hb, hb, 1);
    }

    cudaEventRecord(ev1, s1);
    cudaEventRecord(ev2, s2);
    cudaStreamWaitEvent(0, ev1, 0);
    cudaStreamWaitEvent(0, ev2, 0);

    loss_k<<<gb, 256>>>(gt, info, n, G);
    finalize_k<<<1, 1>>>((float*)d_out);
}